// round 5
// baseline (speedup 1.0000x reference)
#include <cuda_runtime.h>

// ComplexAttention: B=4, S=2048, DIM=1024
// out[2,B,S,D] = softmax_causal((Qcat @ Kcat^T) * D^-0.5) @ [vr|vi]
// where Qcat = [qr|qi], etc., from complex linears of [zr|zi].

#define B_ 4
#define S_ 2048
#define D_ 1024
#define M_ (B_ * S_)   // 8192 rows total
#define TD 2048        // 2*D (concat real|imag)

// Scratch (allocation-free rule: __device__ globals)
__device__ float g_Q[(size_t)M_ * TD];           // 64 MB
__device__ float g_K[(size_t)M_ * TD];           // 64 MB
__device__ float g_V[(size_t)M_ * TD];           // 64 MB
__device__ float g_P[(size_t)B_ * S_ * S_];      // 64 MB (scores -> probs)

#define TM 64
#define TN 64
#define TK 16

// ---------------------------------------------------------------------------
// Kernel 1: fused complex projections.
// C[m, gn] over gn in [0,6144): group = gn/1024 -> (q_r,q_i,k_r,k_i,v_r,v_i)
// y_r = zr@wr^T - zi@wi^T ; y_i = zr@wi^T + zi@wr^T
// Virtual A: k<1024 -> zr, else zi. Virtual B per group with sign on hi half.
// ---------------------------------------------------------------------------
__global__ void __launch_bounds__(256) proj_kernel(
    const float* __restrict__ zr, const float* __restrict__ zi,
    const float* __restrict__ wqr, const float* __restrict__ wqi,
    const float* __restrict__ wkr, const float* __restrict__ wki,
    const float* __restrict__ wvr, const float* __restrict__ wvi)
{
    __shared__ float As[TK][TM];
    __shared__ float Bs[TK][TN];

    const int m0 = blockIdx.y * TM;
    const int gn0 = blockIdx.x * TN;
    const int group = gn0 / D_;        // 0..5 (TN divides 1024 -> no straddle)
    const int nn0 = gn0 % D_;
    const int pair = group >> 1;       // 0=Q 1=K 2=V
    const int is_imag = group & 1;

    const float* wr = (pair == 0) ? wqr : (pair == 1) ? wkr : wvr;
    const float* wi = (pair == 0) ? wqi : (pair == 1) ? wki : wvi;
    const float* w_lo = is_imag ? wi : wr;
    const float* w_hi = is_imag ? wr : wi;
    const float sign_hi = is_imag ? 1.0f : -1.0f;
    float* outbuf = (pair == 0) ? g_Q : (pair == 1) ? g_K : g_V;
    const int colbase = is_imag * D_;

    const int tid = threadIdx.x;
    const int arow = tid >> 2, aq = tid & 3;   // 64 rows x 4 float4 per k-tile
    const int ty = tid >> 4, tx = tid & 15;

    float acc[4][4] = {};

    for (int k0 = 0; k0 < TD; k0 += TK) {
        const float *Ap, *Bp;
        float bsign;
        if (k0 < D_) { Ap = zr + k0;        Bp = w_lo + k0;        bsign = 1.0f; }
        else         { Ap = zi + (k0 - D_); Bp = w_hi + (k0 - D_); bsign = sign_hi; }

        float4 av = *(const float4*)(Ap + (size_t)(m0 + arow) * D_ + aq * 4);
        As[aq * 4 + 0][arow] = av.x; As[aq * 4 + 1][arow] = av.y;
        As[aq * 4 + 2][arow] = av.z; As[aq * 4 + 3][arow] = av.w;
        float4 bv = *(const float4*)(Bp + (size_t)(nn0 + arow) * D_ + aq * 4);
        Bs[aq * 4 + 0][arow] = bv.x * bsign; Bs[aq * 4 + 1][arow] = bv.y * bsign;
        Bs[aq * 4 + 2][arow] = bv.z * bsign; Bs[aq * 4 + 3][arow] = bv.w * bsign;
        __syncthreads();

        #pragma unroll
        for (int kk = 0; kk < TK; kk++) {
            float4 a4 = *(const float4*)&As[kk][ty * 4];
            float4 b4 = *(const float4*)&Bs[kk][tx * 4];
            float a[4] = {a4.x, a4.y, a4.z, a4.w};
            float b[4] = {b4.x, b4.y, b4.z, b4.w};
            #pragma unroll
            for (int i = 0; i < 4; i++)
                #pragma unroll
                for (int j = 0; j < 4; j++)
                    acc[i][j] += a[i] * b[j];
        }
        __syncthreads();
    }

    #pragma unroll
    for (int i = 0; i < 4; i++) {
        const int m = m0 + ty * 4 + i;
        #pragma unroll
        for (int j = 0; j < 4; j++) {
            const int c = colbase + nn0 + tx * 4 + j;
            outbuf[(size_t)m * TD + c] = acc[i][j];
        }
    }
}

// ---------------------------------------------------------------------------
// Kernel 2: scores = (Qcat @ Kcat^T) * scale, per batch, causal block skip.
// Both operands K-major (row-major [rows, TD]).
// ---------------------------------------------------------------------------
__global__ void __launch_bounds__(256) scores_kernel()
{
    const int b = blockIdx.z;
    const int m0 = blockIdx.y * TM;   // query rows
    const int n0 = blockIdx.x * TN;   // key rows
    if (n0 > m0 + (TM - 1)) return;   // fully above diagonal -> masked

    const float* A = g_Q + (size_t)b * S_ * TD;
    const float* Bm = g_K + (size_t)b * S_ * TD;
    float* C = g_P + (size_t)b * S_ * S_;

    __shared__ float As[TK][TM];
    __shared__ float Bs[TK][TN];

    const int tid = threadIdx.x;
    const int arow = tid >> 2, aq = tid & 3;
    const int ty = tid >> 4, tx = tid & 15;

    float acc[4][4] = {};

    for (int k0 = 0; k0 < TD; k0 += TK) {
        float4 av = *(const float4*)(A + (size_t)(m0 + arow) * TD + k0 + aq * 4);
        As[aq * 4 + 0][arow] = av.x; As[aq * 4 + 1][arow] = av.y;
        As[aq * 4 + 2][arow] = av.z; As[aq * 4 + 3][arow] = av.w;
        float4 bv = *(const float4*)(Bm + (size_t)(n0 + arow) * TD + k0 + aq * 4);
        Bs[aq * 4 + 0][arow] = bv.x; Bs[aq * 4 + 1][arow] = bv.y;
        Bs[aq * 4 + 2][arow] = bv.z; Bs[aq * 4 + 3][arow] = bv.w;
        __syncthreads();

        #pragma unroll
        for (int kk = 0; kk < TK; kk++) {
            float4 a4 = *(const float4*)&As[kk][ty * 4];
            float4 b4 = *(const float4*)&Bs[kk][tx * 4];
            float a[4] = {a4.x, a4.y, a4.z, a4.w};
            float b[4] = {b4.x, b4.y, b4.z, b4.w};
            #pragma unroll
            for (int i = 0; i < 4; i++)
                #pragma unroll
                for (int j = 0; j < 4; j++)
                    acc[i][j] += a[i] * b[j];
        }
        __syncthreads();
    }

    const float scale = 0.03125f;  // 1024^-0.5
    #pragma unroll
    for (int i = 0; i < 4; i++) {
        const int m = m0 + ty * 4 + i;
        #pragma unroll
        for (int j = 0; j < 4; j++)
            C[(size_t)m * S_ + n0 + tx * 4 + j] = acc[i][j] * scale;
    }
}

// ---------------------------------------------------------------------------
// Kernel 3: causal row softmax in-place on g_P. Zero-fills j > i so the PV
// GEMM needs no masking. One block per row; 8 elems/thread (2048/256).
// ---------------------------------------------------------------------------
__global__ void __launch_bounds__(256) softmax_kernel()
{
    const int row = blockIdx.x;         // b*S + i
    const int i = row & (S_ - 1);
    float* p = g_P + (size_t)row * S_;
    const int L = i + 1;
    const int tid = threadIdx.x;

    float v[8];
    float tmax = -3.0e38f;
    #pragma unroll
    for (int r = 0; r < 8; r++) {
        const int j = r * 256 + tid;
        if (j < L) { v[r] = p[j]; tmax = fmaxf(tmax, v[r]); }
    }

    __shared__ float red[256];
    red[tid] = tmax; __syncthreads();
    for (int s = 128; s > 0; s >>= 1) {
        if (tid < s) red[tid] = fmaxf(red[tid], red[tid + s]);
        __syncthreads();
    }
    const float mx = red[0];
    __syncthreads();

    float tsum = 0.0f;
    #pragma unroll
    for (int r = 0; r < 8; r++) {
        const int j = r * 256 + tid;
        if (j < L) { v[r] = __expf(v[r] - mx); tsum += v[r]; }
    }
    red[tid] = tsum; __syncthreads();
    for (int s = 128; s > 0; s >>= 1) {
        if (tid < s) red[tid] += red[tid + s];
        __syncthreads();
    }
    const float inv = 1.0f / red[0];

    #pragma unroll
    for (int r = 0; r < 8; r++) {
        const int j = r * 256 + tid;
        p[j] = (j < L) ? v[r] * inv : 0.0f;
    }
}

// ---------------------------------------------------------------------------
// Kernel 4: Out = P @ Vcat per batch, causal K-truncation (k <= m0+63).
// A row-major [S,S] (k contiguous), B row-major [S, TD] (n contiguous).
// C[m, n]: n<1024 -> out_real, else out_imag.
// ---------------------------------------------------------------------------
__global__ void __launch_bounds__(256) out_kernel(float* __restrict__ out)
{
    const int b = blockIdx.z;
    const int m0 = blockIdx.y * TM;
    const int n0 = blockIdx.x * TN;

    const float* A = g_P + (size_t)b * S_ * S_;
    const float* Bm = g_V + (size_t)b * S_ * TD;

    __shared__ float As[TK][TM];
    __shared__ float Bs[TK][TN];

    const int tid = threadIdx.x;
    const int arow = tid >> 2, aq = tid & 3;  // A loads (transpose into smem)
    const int bk = tid >> 4, bq = tid & 15;   // B loads (direct)
    const int ty = tid >> 4, tx = tid & 15;

    float acc[4][4] = {};

    const int kend = m0 + TM;   // P is zero beyond the diagonal; skip dead tiles
    for (int k0 = 0; k0 < kend; k0 += TK) {
        float4 av = *(const float4*)(A + (size_t)(m0 + arow) * S_ + k0 + aq * 4);
        As[aq * 4 + 0][arow] = av.x; As[aq * 4 + 1][arow] = av.y;
        As[aq * 4 + 2][arow] = av.z; As[aq * 4 + 3][arow] = av.w;
        float4 bv = *(const float4*)(Bm + (size_t)(k0 + bk) * TD + n0 + bq * 4);
        *(float4*)&Bs[bk][bq * 4] = bv;
        __syncthreads();

        #pragma unroll
        for (int kk = 0; kk < TK; kk++) {
            float4 a4 = *(const float4*)&As[kk][ty * 4];
            float4 b4 = *(const float4*)&Bs[kk][tx * 4];
            float a[4] = {a4.x, a4.y, a4.z, a4.w};
            float b[4] = {b4.x, b4.y, b4.z, b4.w};
            #pragma unroll
            for (int i = 0; i < 4; i++)
                #pragma unroll
                for (int j = 0; j < 4; j++)
                    acc[i][j] += a[i] * b[j];
        }
        __syncthreads();
    }

    // out layout: [2, B, S, D]
    #pragma unroll
    for (int i = 0; i < 4; i++) {
        const int s = m0 + ty * 4 + i;
        #pragma unroll
        for (int j = 0; j < 4; j++) {
            const int n = n0 + tx * 4 + j;
            const int part = (n >= D_) ? 1 : 0;
            const int d = n - part * D_;
            out[(((size_t)part * B_ + b) * S_ + s) * D_ + d] = acc[i][j];
        }
    }
}

extern "C" void kernel_launch(void* const* d_in, const int* in_sizes, int n_in,
                              void* d_out, int out_size)
{
    const float* zr  = (const float*)d_in[0];
    const float* zi  = (const float*)d_in[1];
    const float* wqr = (const float*)d_in[2];
    const float* wqi = (const float*)d_in[3];
    const float* wkr = (const float*)d_in[4];
    const float* wki = (const float*)d_in[5];
    const float* wvr = (const float*)d_in[6];
    const float* wvi = (const float*)d_in[7];
    // d_in[8] = mask (int32 tril) — structure is causal by construction; unused.
    float* out = (float*)d_out;

    proj_kernel<<<dim3(6144 / TN, M_ / TM), 256>>>(zr, zi, wqr, wqi, wkr, wki, wvr, wvi);
    scores_kernel<<<dim3(S_ / TN, S_ / TM, B_), 256>>>();
    softmax_kernel<<<B_ * S_, 256>>>();
    out_kernel<<<dim3(TD / TN, S_ / TM, B_), 256>>>(out);
}

// round 7
// speedup vs baseline: 1.9178x; 1.9178x over previous
#include <cuda_runtime.h>
#include <cuda_bf16.h>
#include <cstdint>

// ComplexAttention B=4, S=2048, DIM=1024 — split-bf16 mma.sync tensor-core port.
// (tcgen05 is unavailable: harness lowers via compute_103 PTX, which rejects
//  sm_103a-gated features. mma.sync/ldmatrix/cp.async are sm_80 features.)
#define B_ 4
#define S_ 2048
#define D_ 1024
#define M_ (B_ * S_)   // 8192
#define TD 2048        // 2*D

// GEMM tiling
#define BM 128
#define BN 128
#define BK 32
// Smem stage layout (bytes). A/B non-trans tiles: 128 rows x 32 bf16, rows
// padded to 80B (conflict-free ldmatrix: 20*r mod 32 distinct for r=0..7).
// Mode-2 B tile: 32 k-rows x 128 bf16 (256B rows) with 16B-chunk xor swizzle.
#define ST_A_HI 0
#define ST_A_LO 10240
#define ST_B_HI 20480
#define ST_B_LO 30720
#define STAGE_SZ 40960
#define SMEM_TOTAL (2 * STAGE_SZ)   // 81920

// ---------------------------------------------------------------------------
// Scratch (__device__ globals; allocation-free rule)
// ---------------------------------------------------------------------------
__device__ __nv_bfloat16 g_Zhi[(size_t)M_ * TD];
__device__ __nv_bfloat16 g_Zlo[(size_t)M_ * TD];
__device__ __nv_bfloat16 g_Whi[(size_t)3 * TD * TD];   // 6144 x 2048
__device__ __nv_bfloat16 g_Wlo[(size_t)3 * TD * TD];
__device__ __nv_bfloat16 g_Qhi[(size_t)M_ * TD];
__device__ __nv_bfloat16 g_Qlo[(size_t)M_ * TD];
__device__ __nv_bfloat16 g_Khi[(size_t)M_ * TD];
__device__ __nv_bfloat16 g_Klo[(size_t)M_ * TD];
__device__ __nv_bfloat16 g_Vhi[(size_t)M_ * TD];       // natural [b*t][n]
__device__ __nv_bfloat16 g_Vlo[(size_t)M_ * TD];
__device__ float         g_P  [(size_t)B_ * S_ * S_];
__device__ __nv_bfloat16 g_Phi[(size_t)B_ * S_ * S_];
__device__ __nv_bfloat16 g_Plo[(size_t)B_ * S_ * S_];

// ---------------------------------------------------------------------------
// PTX helpers (sm_80-class only)
// ---------------------------------------------------------------------------
__device__ __forceinline__ uint32_t smem_u32(const void* p) {
    uint32_t a;
    asm("{ .reg .u64 t; cvta.to.shared.u64 t, %1; cvt.u32.u64 %0, t; }" : "=r"(a) : "l"(p));
    return a;
}
__device__ __forceinline__ void ldsm_x4(uint32_t* r, uint32_t addr) {
    asm volatile("ldmatrix.sync.aligned.m8n8.x4.shared.b16 {%0,%1,%2,%3}, [%4];"
        : "=r"(r[0]), "=r"(r[1]), "=r"(r[2]), "=r"(r[3]) : "r"(addr));
}
__device__ __forceinline__ void ldsm_x4_t(uint32_t* r, uint32_t addr) {
    asm volatile("ldmatrix.sync.aligned.m8n8.x4.trans.shared.b16 {%0,%1,%2,%3}, [%4];"
        : "=r"(r[0]), "=r"(r[1]), "=r"(r[2]), "=r"(r[3]) : "r"(addr));
}
__device__ __forceinline__ void mma_bf16(float* d, const uint32_t* a, const uint32_t* b) {
    asm volatile(
        "mma.sync.aligned.m16n8k16.row.col.f32.bf16.bf16.f32 "
        "{%0,%1,%2,%3}, {%4,%5,%6,%7}, {%8,%9}, {%0,%1,%2,%3};"
        : "+f"(d[0]), "+f"(d[1]), "+f"(d[2]), "+f"(d[3])
        : "r"(a[0]), "r"(a[1]), "r"(a[2]), "r"(a[3]), "r"(b[0]), "r"(b[1]));
}
#define CP_ASYNC16(dst, src) \
    asm volatile("cp.async.cg.shared.global [%0], [%1], 16;" :: "r"(dst), "l"(src) : "memory")
#define CP_COMMIT() asm volatile("cp.async.commit_group;" ::: "memory")
#define CP_WAIT1()  asm volatile("cp.async.wait_group 1;" ::: "memory")

__device__ __forceinline__ uint32_t pack2(float a, float b) {
    uint16_t la = __bfloat16_as_ushort(__float2bfloat16(a));
    uint16_t lb = __bfloat16_as_ushort(__float2bfloat16(b));
    return (uint32_t)la | ((uint32_t)lb << 16);
}
__device__ __forceinline__ void split_bf(float x, float& h, float& l) {
    h = __bfloat162float(__float2bfloat16(x));
    l = x - h;
}

// ---------------------------------------------------------------------------
// Prep 1: Zcat = [zr|zi] split to bf16 hi/lo. 4 floats/thread.
// ---------------------------------------------------------------------------
__global__ void __launch_bounds__(256) split_z_kernel(const float* __restrict__ zr,
                                                      const float* __restrict__ zi) {
    const int idx = blockIdx.x * 256 + threadIdx.x;
    const int m = idx >> 9, c4 = idx & 511;
    const float* src = (c4 < 256) ? (zr + (size_t)m * D_ + c4 * 4)
                                  : (zi + (size_t)m * D_ + (c4 - 256) * 4);
    float4 x = *(const float4*)src;
    float h0, h1, h2, h3, l0, l1, l2, l3;
    split_bf(x.x, h0, l0); split_bf(x.y, h1, l1);
    split_bf(x.z, h2, l2); split_bf(x.w, h3, l3);
    const size_t o = (size_t)m * TD + c4 * 4;
    *(uint2*)(g_Zhi + o) = make_uint2(pack2(h0, h1), pack2(h2, h3));
    *(uint2*)(g_Zlo + o) = make_uint2(pack2(l0, l1), pack2(l2, l3));
}

// ---------------------------------------------------------------------------
// Prep 2: Wcat [6144 x 2048] with signs, split bf16 hi/lo.
// ---------------------------------------------------------------------------
__global__ void __launch_bounds__(256) build_w_kernel(
    const float* __restrict__ wqr, const float* __restrict__ wqi,
    const float* __restrict__ wkr, const float* __restrict__ wki,
    const float* __restrict__ wvr, const float* __restrict__ wvi) {
    const int idx = blockIdx.x * 256 + threadIdx.x;
    const int gn = idx >> 9, c4 = idx & 511;
    const int pair = gn >> 11, is_imag = (gn >> 10) & 1, nn = gn & 1023;
    const float* wr = (pair == 0) ? wqr : (pair == 1) ? wkr : wvr;
    const float* wi = (pair == 0) ? wqi : (pair == 1) ? wki : wvi;
    const float* wl = is_imag ? wi : wr;
    const float* wh = is_imag ? wr : wi;
    float4 x;
    if (c4 < 256) {
        x = *(const float4*)(wl + (size_t)nn * D_ + c4 * 4);
    } else {
        x = *(const float4*)(wh + (size_t)nn * D_ + (c4 - 256) * 4);
        const float s = is_imag ? 1.0f : -1.0f;
        x.x *= s; x.y *= s; x.z *= s; x.w *= s;
    }
    float h0, h1, h2, h3, l0, l1, l2, l3;
    split_bf(x.x, h0, l0); split_bf(x.y, h1, l1);
    split_bf(x.z, h2, l2); split_bf(x.w, h3, l3);
    const size_t o = (size_t)gn * TD + c4 * 4;
    *(uint2*)(g_Whi + o) = make_uint2(pack2(h0, h1), pack2(h2, h3));
    *(uint2*)(g_Wlo + o) = make_uint2(pack2(l0, l1), pack2(l2, l3));
}

// ---------------------------------------------------------------------------
// Split-bf16 tensor-core GEMM. MODE: 0=proj  1=scores  2=PV
// C[128x128] = sum of (AhiBhi + AhiBlo + AloBhi), fp32 accum via mma.sync.
// All operand row strides are 2048 elements.
// MODE 0/1: B operand stored [n][k] (K-contig)  -> ldmatrix non-trans
// MODE 2:   B operand stored [k][n] (V natural) -> ldmatrix .trans
// ---------------------------------------------------------------------------
template <int MODE>
__global__ void __launch_bounds__(256, 1)
gemm_kernel(float* __restrict__ outp) {
    extern __shared__ char smem[];
    const uint32_t sbase = smem_u32(smem);
    const int tid = threadIdx.x;
    const int wid = tid >> 5, lane = tid & 31;
    const int wm = (wid & 3) * 32;        // warp row base within tile
    const int wn = (wid >> 2) * 64;       // warp col base within tile
    const int tr = lane >> 2, tc = lane & 3;

    int m0, n0, kend, b = 0;
    const __nv_bfloat16 *Ahi_, *Alo_, *Bhi_, *Blo_;
    if (MODE == 0) {
        m0 = blockIdx.y * BM; n0 = blockIdx.x * BN; kend = TD;
        Ahi_ = g_Zhi; Alo_ = g_Zlo; Bhi_ = g_Whi; Blo_ = g_Wlo;
    } else if (MODE == 1) {
        b = blockIdx.z; m0 = blockIdx.y * BM; n0 = blockIdx.x * BN;
        if (n0 > m0 + BM - 1) return;     // fully above diagonal
        kend = TD;
        Ahi_ = g_Qhi + (size_t)b * S_ * TD; Alo_ = g_Qlo + (size_t)b * S_ * TD;
        Bhi_ = g_Khi + (size_t)b * S_ * TD; Blo_ = g_Klo + (size_t)b * S_ * TD;
    } else {
        b = blockIdx.z; m0 = blockIdx.y * BM; n0 = blockIdx.x * BN;
        kend = m0 + BM;                   // P zero beyond diagonal
        Ahi_ = g_Phi + (size_t)b * S_ * S_; Alo_ = g_Plo + (size_t)b * S_ * S_;
        Bhi_ = g_Vhi + (size_t)b * S_ * TD; Blo_ = g_Vlo + (size_t)b * S_ * TD;
    }

    const int nch = kend / BK;

    // ---- async chunk loader ----
    auto load_chunk = [&](int c, int st) {
        const int k0 = c * BK;
        const uint32_t so = sbase + st * STAGE_SZ;
#pragma unroll
        for (int i = 0; i < 2; i++) {
            const int s = i * 256 + tid;
            const int row = s >> 2, ch = s & 3;
            const size_t go = (size_t)(m0 + row) * TD + k0 + ch * 8;
            const uint32_t dA = so + ST_A_HI + row * 80 + ch * 16;
            CP_ASYNC16(dA, Ahi_ + go);
            CP_ASYNC16(dA + (ST_A_LO - ST_A_HI), Alo_ + go);
        }
        if (MODE != 2) {
#pragma unroll
            for (int i = 0; i < 2; i++) {
                const int s = i * 256 + tid;
                const int row = s >> 2, ch = s & 3;
                const size_t go = (size_t)(n0 + row) * TD + k0 + ch * 8;
                const uint32_t dB = so + ST_B_HI + row * 80 + ch * 16;
                CP_ASYNC16(dB, Bhi_ + go);
                CP_ASYNC16(dB + (ST_B_LO - ST_B_HI), Blo_ + go);
            }
        } else {
#pragma unroll
            for (int i = 0; i < 2; i++) {
                const int s = i * 256 + tid;
                const int k = s >> 4, ch = s & 15;
                const size_t go = (size_t)(k0 + k) * TD + n0 + ch * 8;
                const uint32_t dB = so + ST_B_HI + k * 256 + ((ch ^ (k & 7)) * 16);
                CP_ASYNC16(dB, Bhi_ + go);
                CP_ASYNC16(dB + (ST_B_LO - ST_B_HI), Blo_ + go);
            }
        }
    };

    float acc[2][8][4] = {};

    load_chunk(0, 0);
    CP_COMMIT();

#pragma unroll 1
    for (int c = 0; c < nch; c++) {
        if (c + 1 < nch) load_chunk(c + 1, (c + 1) & 1);
        CP_COMMIT();
        CP_WAIT1();
        __syncthreads();

        const uint32_t so = sbase + (c & 1) * STAGE_SZ;
        const uint32_t sA = so + ST_A_HI;
        const uint32_t sB = so + ST_B_HI;

#pragma unroll
        for (int ks = 0; ks < 2; ks++) {
            uint32_t ahi[2][4], alo[2][4], bhi[4][4], blo[4][4];
#pragma unroll
            for (int mt = 0; mt < 2; mt++) {
                const uint32_t ad = sA + (wm + mt * 16 + (lane & 15)) * 80
                                       + (ks * 2 + (lane >> 4)) * 16;
                ldsm_x4(ahi[mt], ad);
                ldsm_x4(alo[mt], ad + (ST_A_LO - ST_A_HI));
            }
            if (MODE != 2) {
#pragma unroll
                for (int bp = 0; bp < 4; bp++) {
                    const int nt = bp * 2 + (lane >> 4);
                    const uint32_t bd = sB + (wn + nt * 8 + (lane & 7)) * 80
                                           + (ks * 2 + ((lane >> 3) & 1)) * 16;
                    ldsm_x4(bhi[bp], bd);
                    ldsm_x4(blo[bp], bd + (ST_B_LO - ST_B_HI));
                }
            } else {
                const int k = ks * 16 + (lane & 15);
#pragma unroll
                for (int bp = 0; bp < 4; bp++) {
                    const int cch = (wn >> 3) + bp * 2 + (lane >> 4);
                    const uint32_t bd = sB + k * 256 + ((cch ^ (k & 7)) * 16);
                    ldsm_x4_t(bhi[bp], bd);
                    ldsm_x4_t(blo[bp], bd + (ST_B_LO - ST_B_HI));
                }
            }
            // phase 1: Ahi * Bhi (16 independent mma)
#pragma unroll
            for (int mt = 0; mt < 2; mt++)
#pragma unroll
                for (int bp = 0; bp < 4; bp++)
#pragma unroll
                    for (int h = 0; h < 2; h++)
                        mma_bf16(acc[mt][bp * 2 + h], ahi[mt], &bhi[bp][h * 2]);
            // phase 2: Ahi * Blo
#pragma unroll
            for (int mt = 0; mt < 2; mt++)
#pragma unroll
                for (int bp = 0; bp < 4; bp++)
#pragma unroll
                    for (int h = 0; h < 2; h++)
                        mma_bf16(acc[mt][bp * 2 + h], ahi[mt], &blo[bp][h * 2]);
            // phase 3: Alo * Bhi
#pragma unroll
            for (int mt = 0; mt < 2; mt++)
#pragma unroll
                for (int bp = 0; bp < 4; bp++)
#pragma unroll
                    for (int h = 0; h < 2; h++)
                        mma_bf16(acc[mt][bp * 2 + h], alo[mt], &bhi[bp][h * 2]);
        }
        __syncthreads();
    }

    // ---- Epilogue (register -> gmem, no smem) ----
    if (MODE == 0) {
        const int group = n0 >> 10;
        const int pair = group >> 1, colbase = (group & 1) << 10;
        __nv_bfloat16* Dh = (pair == 0) ? g_Qhi : (pair == 1) ? g_Khi : g_Vhi;
        __nv_bfloat16* Dl = (pair == 0) ? g_Qlo : (pair == 1) ? g_Klo : g_Vlo;
        const int nbase = colbase + (n0 & 1023) + wn;
#pragma unroll
        for (int mt = 0; mt < 2; mt++)
#pragma unroll
            for (int nt = 0; nt < 8; nt++) {
                const int col = nbase + nt * 8 + tc * 2;
#pragma unroll
                for (int h = 0; h < 2; h++) {
                    const int row = m0 + wm + mt * 16 + tr + h * 8;
                    const float v0 = acc[mt][nt][h * 2 + 0];
                    const float v1 = acc[mt][nt][h * 2 + 1];
                    float h0, h1, l0, l1;
                    split_bf(v0, h0, l0); split_bf(v1, h1, l1);
                    const size_t o = (size_t)row * TD + col;
                    *(uint32_t*)(Dh + o) = pack2(h0, h1);
                    *(uint32_t*)(Dl + o) = pack2(l0, l1);
                }
            }
    } else if (MODE == 1) {
        const float scale = 0.03125f;  // 1024^-0.5
        float* C = g_P + (size_t)b * S_ * S_;
#pragma unroll
        for (int mt = 0; mt < 2; mt++)
#pragma unroll
            for (int nt = 0; nt < 8; nt++) {
                const int col = n0 + wn + nt * 8 + tc * 2;
#pragma unroll
                for (int h = 0; h < 2; h++) {
                    const int row = m0 + wm + mt * 16 + tr + h * 8;
                    float2 v = make_float2(acc[mt][nt][h * 2 + 0] * scale,
                                           acc[mt][nt][h * 2 + 1] * scale);
                    *(float2*)(C + (size_t)row * S_ + col) = v;
                }
            }
    } else {
#pragma unroll
        for (int mt = 0; mt < 2; mt++)
#pragma unroll
            for (int nt = 0; nt < 8; nt++) {
                const int n = n0 + wn + nt * 8 + tc * 2;
                const int part = n >> 10, d = n & 1023;
#pragma unroll
                for (int h = 0; h < 2; h++) {
                    const int s = m0 + wm + mt * 16 + tr + h * 8;
                    float2 v = make_float2(acc[mt][nt][h * 2 + 0],
                                           acc[mt][nt][h * 2 + 1]);
                    *(float2*)(outp + (((size_t)part * B_ + b) * S_ + s) * D_ + d) = v;
                }
            }
    }
}

// ---------------------------------------------------------------------------
// Causal row softmax on fp32 g_P; writes bf16 hi/lo split (zero past diag).
// ---------------------------------------------------------------------------
__global__ void __launch_bounds__(256) softmax_split_kernel() {
    const int row = blockIdx.x;            // b*S + i
    const int i = row & (S_ - 1);
    const float* p = g_P + (size_t)row * S_;
    __nv_bfloat16* ph = g_Phi + (size_t)row * S_;
    __nv_bfloat16* pl = g_Plo + (size_t)row * S_;
    const int L = i + 1;
    const int tid = threadIdx.x;

    float v[8];
    float tmax = -3.0e38f;
#pragma unroll
    for (int r = 0; r < 8; r++) {
        const int j = r * 256 + tid;
        if (j < L) { v[r] = p[j]; tmax = fmaxf(tmax, v[r]); }
    }
    __shared__ float red[256];
    red[tid] = tmax; __syncthreads();
    for (int s = 128; s > 0; s >>= 1) {
        if (tid < s) red[tid] = fmaxf(red[tid], red[tid + s]);
        __syncthreads();
    }
    const float mx = red[0];
    __syncthreads();

    float tsum = 0.0f;
#pragma unroll
    for (int r = 0; r < 8; r++) {
        const int j = r * 256 + tid;
        if (j < L) { v[r] = __expf(v[r] - mx); tsum += v[r]; }
    }
    red[tid] = tsum; __syncthreads();
    for (int s = 128; s > 0; s >>= 1) {
        if (tid < s) red[tid] += red[tid + s];
        __syncthreads();
    }
    const float inv = 1.0f / red[0];

#pragma unroll
    for (int r = 0; r < 8; r++) {
        const int j = r * 256 + tid;
        float hv = 0.0f, lv = 0.0f;
        if (j < L) {
            const float pv = v[r] * inv;
            split_bf(pv, hv, lv);
        }
        ph[j] = __float2bfloat16(hv);
        pl[j] = __float2bfloat16(lv);
    }
}

// ---------------------------------------------------------------------------
extern "C" void kernel_launch(void* const* d_in, const int* in_sizes, int n_in,
                              void* d_out, int out_size) {
    const float* zr  = (const float*)d_in[0];
    const float* zi  = (const float*)d_in[1];
    const float* wqr = (const float*)d_in[2];
    const float* wqi = (const float*)d_in[3];
    const float* wkr = (const float*)d_in[4];
    const float* wki = (const float*)d_in[5];
    const float* wvr = (const float*)d_in[6];
    const float* wvi = (const float*)d_in[7];
    // d_in[8] = tril mask — causal by construction; unused.
    float* out = (float*)d_out;

    cudaFuncSetAttribute(gemm_kernel<0>, cudaFuncAttributeMaxDynamicSharedMemorySize, SMEM_TOTAL);
    cudaFuncSetAttribute(gemm_kernel<1>, cudaFuncAttributeMaxDynamicSharedMemorySize, SMEM_TOTAL);
    cudaFuncSetAttribute(gemm_kernel<2>, cudaFuncAttributeMaxDynamicSharedMemorySize, SMEM_TOTAL);

    split_z_kernel<<<(M_ * TD / 4) / 256, 256>>>(zr, zi);
    build_w_kernel<<<(3 * TD * TD / 4) / 256, 256>>>(wqr, wqi, wkr, wki, wvr, wvi);
    gemm_kernel<0><<<dim3(3 * TD / BN, M_ / BM), 256, SMEM_TOTAL>>>(nullptr);
    gemm_kernel<1><<<dim3(S_ / BN, S_ / BM, B_), 256, SMEM_TOTAL>>>(nullptr);
    softmax_split_kernel<<<B_ * S_, 256>>>();
    gemm_kernel<2><<<dim3(TD / BN, S_ / BM, B_), 256, SMEM_TOTAL>>>(out);
}

// round 10
// speedup vs baseline: 3.1548x; 1.6450x over previous
#include <cuda_runtime.h>
#include <cuda_bf16.h>
#include <cstdint>

// ComplexAttention B=4, S=2048, DIM=1024 — split-bf16 mma.sync tensor-core port.
// R8: 4-stage cp.async pipeline, 1 barrier/chunk, triangular scores launch.
#define B_ 4
#define S_ 2048
#define D_ 1024
#define M_ (B_ * S_)   // 8192
#define TD 2048        // 2*D

// GEMM tiling
#define BM 128
#define BN 128
#define BK 32
#define NSTAGE 4
// Smem stage layout (bytes). A/B non-trans tiles: 128 rows x 32 bf16, rows
// padded to 80B (conflict-free ldmatrix). Mode-2 B tile: 32 k-rows x 128 bf16
// (256B rows) with 16B-chunk xor swizzle.
#define ST_A_HI 0
#define ST_A_LO 10240
#define ST_B_HI 20480
#define ST_B_LO 30720
#define STAGE_SZ 40960
#define SMEM_TOTAL (NSTAGE * STAGE_SZ)   // 163840

// ---------------------------------------------------------------------------
// Scratch (__device__ globals; allocation-free rule)
// ---------------------------------------------------------------------------
__device__ __nv_bfloat16 g_Zhi[(size_t)M_ * TD];
__device__ __nv_bfloat16 g_Zlo[(size_t)M_ * TD];
__device__ __nv_bfloat16 g_Whi[(size_t)3 * TD * TD];   // 6144 x 2048
__device__ __nv_bfloat16 g_Wlo[(size_t)3 * TD * TD];
__device__ __nv_bfloat16 g_Qhi[(size_t)M_ * TD];
__device__ __nv_bfloat16 g_Qlo[(size_t)M_ * TD];
__device__ __nv_bfloat16 g_Khi[(size_t)M_ * TD];
__device__ __nv_bfloat16 g_Klo[(size_t)M_ * TD];
__device__ __nv_bfloat16 g_Vhi[(size_t)M_ * TD];       // natural [b*t][n]
__device__ __nv_bfloat16 g_Vlo[(size_t)M_ * TD];
__device__ float         g_P  [(size_t)B_ * S_ * S_];
__device__ __nv_bfloat16 g_Phi[(size_t)B_ * S_ * S_];
__device__ __nv_bfloat16 g_Plo[(size_t)B_ * S_ * S_];

// ---------------------------------------------------------------------------
// PTX helpers (sm_80-class only)
// ---------------------------------------------------------------------------
__device__ __forceinline__ uint32_t smem_u32(const void* p) {
    uint32_t a;
    asm("{ .reg .u64 t; cvta.to.shared.u64 t, %1; cvt.u32.u64 %0, t; }" : "=r"(a) : "l"(p));
    return a;
}
__device__ __forceinline__ void ldsm_x4(uint32_t* r, uint32_t addr) {
    asm volatile("ldmatrix.sync.aligned.m8n8.x4.shared.b16 {%0,%1,%2,%3}, [%4];"
        : "=r"(r[0]), "=r"(r[1]), "=r"(r[2]), "=r"(r[3]) : "r"(addr));
}
__device__ __forceinline__ void ldsm_x4_t(uint32_t* r, uint32_t addr) {
    asm volatile("ldmatrix.sync.aligned.m8n8.x4.trans.shared.b16 {%0,%1,%2,%3}, [%4];"
        : "=r"(r[0]), "=r"(r[1]), "=r"(r[2]), "=r"(r[3]) : "r"(addr));
}
__device__ __forceinline__ void mma_bf16(float* d, const uint32_t* a, const uint32_t* b) {
    asm volatile(
        "mma.sync.aligned.m16n8k16.row.col.f32.bf16.bf16.f32 "
        "{%0,%1,%2,%3}, {%4,%5,%6,%7}, {%8,%9}, {%0,%1,%2,%3};"
        : "+f"(d[0]), "+f"(d[1]), "+f"(d[2]), "+f"(d[3])
        : "r"(a[0]), "r"(a[1]), "r"(a[2]), "r"(a[3]), "r"(b[0]), "r"(b[1]));
}
#define CP_ASYNC16(dst, src) \
    asm volatile("cp.async.cg.shared.global [%0], [%1], 16;" :: "r"(dst), "l"(src) : "memory")
#define CP_COMMIT() asm volatile("cp.async.commit_group;" ::: "memory")
#define CP_WAITG2() asm volatile("cp.async.wait_group 2;" ::: "memory")

__device__ __forceinline__ uint32_t pack2(float a, float b) {
    uint16_t la = __bfloat16_as_ushort(__float2bfloat16(a));
    uint16_t lb = __bfloat16_as_ushort(__float2bfloat16(b));
    return (uint32_t)la | ((uint32_t)lb << 16);
}
__device__ __forceinline__ void split_bf(float x, float& h, float& l) {
    h = __bfloat162float(__float2bfloat16(x));
    l = x - h;
}

// ---------------------------------------------------------------------------
// Prep 1: Zcat = [zr|zi] split to bf16 hi/lo. 4 floats/thread.
// ---------------------------------------------------------------------------
__global__ void __launch_bounds__(256) split_z_kernel(const float* __restrict__ zr,
                                                      const float* __restrict__ zi) {
    const int idx = blockIdx.x * 256 + threadIdx.x;
    const int m = idx >> 9, c4 = idx & 511;
    const float* src = (c4 < 256) ? (zr + (size_t)m * D_ + c4 * 4)
                                  : (zi + (size_t)m * D_ + (c4 - 256) * 4);
    float4 x = *(const float4*)src;
    float h0, h1, h2, h3, l0, l1, l2, l3;
    split_bf(x.x, h0, l0); split_bf(x.y, h1, l1);
    split_bf(x.z, h2, l2); split_bf(x.w, h3, l3);
    const size_t o = (size_t)m * TD + c4 * 4;
    *(uint2*)(g_Zhi + o) = make_uint2(pack2(h0, h1), pack2(h2, h3));
    *(uint2*)(g_Zlo + o) = make_uint2(pack2(l0, l1), pack2(l2, l3));
}

// ---------------------------------------------------------------------------
// Prep 2: Wcat [6144 x 2048] with signs, split bf16 hi/lo.
// ---------------------------------------------------------------------------
__global__ void __launch_bounds__(256) build_w_kernel(
    const float* __restrict__ wqr, const float* __restrict__ wqi,
    const float* __restrict__ wkr, const float* __restrict__ wki,
    const float* __restrict__ wvr, const float* __restrict__ wvi) {
    const int idx = blockIdx.x * 256 + threadIdx.x;
    const int gn = idx >> 9, c4 = idx & 511;
    const int pair = gn >> 11, is_imag = (gn >> 10) & 1, nn = gn & 1023;
    const float* wr = (pair == 0) ? wqr : (pair == 1) ? wkr : wvr;
    const float* wi = (pair == 0) ? wqi : (pair == 1) ? wki : wvi;
    const float* wl = is_imag ? wi : wr;
    const float* wh = is_imag ? wr : wi;
    float4 x;
    if (c4 < 256) {
        x = *(const float4*)(wl + (size_t)nn * D_ + c4 * 4);
    } else {
        x = *(const float4*)(wh + (size_t)nn * D_ + (c4 - 256) * 4);
        const float s = is_imag ? 1.0f : -1.0f;
        x.x *= s; x.y *= s; x.z *= s; x.w *= s;
    }
    float h0, h1, h2, h3, l0, l1, l2, l3;
    split_bf(x.x, h0, l0); split_bf(x.y, h1, l1);
    split_bf(x.z, h2, l2); split_bf(x.w, h3, l3);
    const size_t o = (size_t)gn * TD + c4 * 4;
    *(uint2*)(g_Whi + o) = make_uint2(pack2(h0, h1), pack2(h2, h3));
    *(uint2*)(g_Wlo + o) = make_uint2(pack2(l0, l1), pack2(l2, l3));
}

// ---------------------------------------------------------------------------
// Split-bf16 tensor-core GEMM. MODE: 0=proj  1=scores  2=PV
// C[128x128] = AhiBhi + AhiBlo + AloBhi, fp32 accum via mma.sync.
// MODE 0/1: B stored [n][k] (K-contig) -> ldmatrix non-trans
// MODE 2:   B stored [k][n] (V natural) -> ldmatrix .trans
// 4-stage cp.async ring; one __syncthreads per chunk.
// ---------------------------------------------------------------------------
template <int MODE>
__global__ void __launch_bounds__(256, 1)
gemm_kernel(float* __restrict__ outp) {
    extern __shared__ char smem[];
    const uint32_t sbase = smem_u32(smem);
    const int tid = threadIdx.x;
    const int wid = tid >> 5, lane = tid & 31;
    const int wm = (wid & 3) * 32;        // warp row base within tile
    const int wn = (wid >> 2) * 64;       // warp col base within tile
    const int tr = lane >> 2, tc = lane & 3;

    int m0, n0, kend, b = 0;
    const __nv_bfloat16 *Ahi_, *Alo_, *Bhi_, *Blo_;
    if (MODE == 0) {
        m0 = blockIdx.y * BM; n0 = blockIdx.x * BN; kend = TD;
        Ahi_ = g_Zhi; Alo_ = g_Zlo; Bhi_ = g_Whi; Blo_ = g_Wlo;
    } else if (MODE == 1) {
        b = blockIdx.z;
        // triangular launch: x in [0,136) -> (r, c) with c <= r
        const int x = blockIdx.x;
        int r = (int)((sqrtf(8.0f * x + 1.0f) - 1.0f) * 0.5f);
        while ((r + 1) * (r + 2) / 2 <= x) r++;
        while (r * (r + 1) / 2 > x) r--;
        m0 = r * BM; n0 = (x - r * (r + 1) / 2) * BN;
        kend = TD;
        Ahi_ = g_Qhi + (size_t)b * S_ * TD; Alo_ = g_Qlo + (size_t)b * S_ * TD;
        Bhi_ = g_Khi + (size_t)b * S_ * TD; Blo_ = g_Klo + (size_t)b * S_ * TD;
    } else {
        b = blockIdx.z; m0 = blockIdx.y * BM; n0 = blockIdx.x * BN;
        kend = m0 + BM;                   // P zero beyond diagonal
        Ahi_ = g_Phi + (size_t)b * S_ * S_; Alo_ = g_Plo + (size_t)b * S_ * S_;
        Bhi_ = g_Vhi + (size_t)b * S_ * TD; Blo_ = g_Vlo + (size_t)b * S_ * TD;
    }

    const int nch = kend / BK;   // >= 4 in all modes

    // ---- async chunk loader ----
    auto load_chunk = [&](int c, int st) {
        const int k0 = c * BK;
        const uint32_t so = sbase + st * STAGE_SZ;
#pragma unroll
        for (int i = 0; i < 2; i++) {
            const int s = i * 256 + tid;
            const int row = s >> 2, ch = s & 3;
            const size_t go = (size_t)(m0 + row) * TD + k0 + ch * 8;
            const uint32_t dA = so + ST_A_HI + row * 80 + ch * 16;
            CP_ASYNC16(dA, Ahi_ + go);
            CP_ASYNC16(dA + (ST_A_LO - ST_A_HI), Alo_ + go);
        }
        if (MODE != 2) {
#pragma unroll
            for (int i = 0; i < 2; i++) {
                const int s = i * 256 + tid;
                const int row = s >> 2, ch = s & 3;
                const size_t go = (size_t)(n0 + row) * TD + k0 + ch * 8;
                const uint32_t dB = so + ST_B_HI + row * 80 + ch * 16;
                CP_ASYNC16(dB, Bhi_ + go);
                CP_ASYNC16(dB + (ST_B_LO - ST_B_HI), Blo_ + go);
            }
        } else {
#pragma unroll
            for (int i = 0; i < 2; i++) {
                const int s = i * 256 + tid;
                const int k = s >> 4, ch = s & 15;
                const size_t go = (size_t)(k0 + k) * TD + n0 + ch * 8;
                const uint32_t dB = so + ST_B_HI + k * 256 + ((ch ^ (k & 7)) * 16);
                CP_ASYNC16(dB, Bhi_ + go);
                CP_ASYNC16(dB + (ST_B_LO - ST_B_HI), Blo_ + go);
            }
        }
    };

    float acc[2][8][4] = {};

    // preload 3 chunks
#pragma unroll
    for (int c = 0; c < 3; c++) { load_chunk(c, c); CP_COMMIT(); }

#pragma unroll 1
    for (int c = 0; c < nch; c++) {
        CP_WAITG2();            // chunk c landed
        __syncthreads();        // also: stage (c+3)&3 = (c-1)&3 fully consumed
        if (c + 3 < nch) load_chunk(c + 3, (c + 3) & 3);
        CP_COMMIT();

        const uint32_t so = sbase + (c & 3) * STAGE_SZ;
        const uint32_t sA = so + ST_A_HI;
        const uint32_t sB = so + ST_B_HI;

#pragma unroll
        for (int ks = 0; ks < 2; ks++) {
            uint32_t ahi[2][4], alo[2][4], bhi[4][4], blo[4][4];
#pragma unroll
            for (int mt = 0; mt < 2; mt++) {
                const uint32_t ad = sA + (wm + mt * 16 + (lane & 15)) * 80
                                       + (ks * 2 + (lane >> 4)) * 16;
                ldsm_x4(ahi[mt], ad);
                ldsm_x4(alo[mt], ad + (ST_A_LO - ST_A_HI));
            }
            if (MODE != 2) {
#pragma unroll
                for (int bp = 0; bp < 4; bp++) {
                    const int nt = bp * 2 + (lane >> 4);
                    const uint32_t bd = sB + (wn + nt * 8 + (lane & 7)) * 80
                                           + (ks * 2 + ((lane >> 3) & 1)) * 16;
                    ldsm_x4(bhi[bp], bd);
                    ldsm_x4(blo[bp], bd + (ST_B_LO - ST_B_HI));
                }
            } else {
                const int k = ks * 16 + (lane & 15);
#pragma unroll
                for (int bp = 0; bp < 4; bp++) {
                    const int cch = (wn >> 3) + bp * 2 + (lane >> 4);
                    const uint32_t bd = sB + k * 256 + ((cch ^ (k & 7)) * 16);
                    ldsm_x4_t(bhi[bp], bd);
                    ldsm_x4_t(blo[bp], bd + (ST_B_LO - ST_B_HI));
                }
            }
            // phase 1: Ahi * Bhi
#pragma unroll
            for (int mt = 0; mt < 2; mt++)
#pragma unroll
                for (int bp = 0; bp < 4; bp++)
#pragma unroll
                    for (int h = 0; h < 2; h++)
                        mma_bf16(acc[mt][bp * 2 + h], ahi[mt], &bhi[bp][h * 2]);
            // phase 2: Ahi * Blo
#pragma unroll
            for (int mt = 0; mt < 2; mt++)
#pragma unroll
                for (int bp = 0; bp < 4; bp++)
#pragma unroll
                    for (int h = 0; h < 2; h++)
                        mma_bf16(acc[mt][bp * 2 + h], ahi[mt], &blo[bp][h * 2]);
            // phase 3: Alo * Bhi
#pragma unroll
            for (int mt = 0; mt < 2; mt++)
#pragma unroll
                for (int bp = 0; bp < 4; bp++)
#pragma unroll
                    for (int h = 0; h < 2; h++)
                        mma_bf16(acc[mt][bp * 2 + h], alo[mt], &bhi[bp][h * 2]);
        }
    }

    // ---- Epilogue (register -> gmem, no smem) ----
    if (MODE == 0) {
        const int group = n0 >> 10;
        const int pair = group >> 1, colbase = (group & 1) << 10;
        __nv_bfloat16* Dh = (pair == 0) ? g_Qhi : (pair == 1) ? g_Khi : g_Vhi;
        __nv_bfloat16* Dl = (pair == 0) ? g_Qlo : (pair == 1) ? g_Klo : g_Vlo;
        const int nbase = colbase + (n0 & 1023) + wn;
#pragma unroll
        for (int mt = 0; mt < 2; mt++)
#pragma unroll
            for (int nt = 0; nt < 8; nt++) {
                const int col = nbase + nt * 8 + tc * 2;
#pragma unroll
                for (int h = 0; h < 2; h++) {
                    const int row = m0 + wm + mt * 16 + tr + h * 8;
                    const float v0 = acc[mt][nt][h * 2 + 0];
                    const float v1 = acc[mt][nt][h * 2 + 1];
                    float h0, h1, l0, l1;
                    split_bf(v0, h0, l0); split_bf(v1, h1, l1);
                    const size_t o = (size_t)row * TD + col;
                    *(uint32_t*)(Dh + o) = pack2(h0, h1);
                    *(uint32_t*)(Dl + o) = pack2(l0, l1);
                }
            }
    } else if (MODE == 1) {
        const float scale = 0.03125f;  // 1024^-0.5
        float* C = g_P + (size_t)b * S_ * S_;
#pragma unroll
        for (int mt = 0; mt < 2; mt++)
#pragma unroll
            for (int nt = 0; nt < 8; nt++) {
                const int col = n0 + wn + nt * 8 + tc * 2;
#pragma unroll
                for (int h = 0; h < 2; h++) {
                    const int row = m0 + wm + mt * 16 + tr + h * 8;
                    float2 v = make_float2(acc[mt][nt][h * 2 + 0] * scale,
                                           acc[mt][nt][h * 2 + 1] * scale);
                    *(float2*)(C + (size_t)row * S_ + col) = v;
                }
            }
    } else {
#pragma unroll
        for (int mt = 0; mt < 2; mt++)
#pragma unroll
            for (int nt = 0; nt < 8; nt++) {
                const int n = n0 + wn + nt * 8 + tc * 2;
                const int part = n >> 10, d = n & 1023;
#pragma unroll
                for (int h = 0; h < 2; h++) {
                    const int s = m0 + wm + mt * 16 + tr + h * 8;
                    float2 v = make_float2(acc[mt][nt][h * 2 + 0],
                                           acc[mt][nt][h * 2 + 1]);
                    *(float2*)(outp + (((size_t)part * B_ + b) * S_ + s) * D_ + d) = v;
                }
            }
    }
}

// ---------------------------------------------------------------------------
// Causal row softmax on fp32 g_P; writes bf16 hi/lo split (zero past diag).
// ---------------------------------------------------------------------------
__global__ void __launch_bounds__(256) softmax_split_kernel() {
    const int row = blockIdx.x;            // b*S + i
    const int i = row & (S_ - 1);
    const float* p = g_P + (size_t)row * S_;
    __nv_bfloat16* ph = g_Phi + (size_t)row * S_;
    __nv_bfloat16* pl = g_Plo + (size_t)row * S_;
    const int L = i + 1;
    const int tid = threadIdx.x;

    float v[8];
    float tmax = -3.0e38f;
#pragma unroll
    for (int r = 0; r < 8; r++) {
        const int j = r * 256 + tid;
        if (j < L) { v[r] = p[j]; tmax = fmaxf(tmax, v[r]); }
    }
    __shared__ float red[256];
    red[tid] = tmax; __syncthreads();
    for (int s = 128; s > 0; s >>= 1) {
        if (tid < s) red[tid] = fmaxf(red[tid], red[tid + s]);
        __syncthreads();
    }
    const float mx = red[0];
    __syncthreads();

    float tsum = 0.0f;
#pragma unroll
    for (int r = 0; r < 8; r++) {
        const int j = r * 256 + tid;
        if (j < L) { v[r] = __expf(v[r] - mx); tsum += v[r]; }
    }
    red[tid] = tsum; __syncthreads();
    for (int s = 128; s > 0; s >>= 1) {
        if (tid < s) red[tid] += red[tid + s];
        __syncthreads();
    }
    const float inv = 1.0f / red[0];

#pragma unroll
    for (int r = 0; r < 8; r++) {
        const int j = r * 256 + tid;
        float hv = 0.0f, lv = 0.0f;
        if (j < L) {
            const float pv = v[r] * inv;
            split_bf(pv, hv, lv);
        }
        ph[j] = __float2bfloat16(hv);
        pl[j] = __float2bfloat16(lv);
    }
}

// ---------------------------------------------------------------------------
extern "C" void kernel_launch(void* const* d_in, const int* in_sizes, int n_in,
                              void* d_out, int out_size) {
    const float* zr  = (const float*)d_in[0];
    const float* zi  = (const float*)d_in[1];
    const float* wqr = (const float*)d_in[2];
    const float* wqi = (const float*)d_in[3];
    const float* wkr = (const float*)d_in[4];
    const float* wki = (const float*)d_in[5];
    const float* wvr = (const float*)d_in[6];
    const float* wvi = (const float*)d_in[7];
    // d_in[8] = tril mask — causal by construction; unused.
    float* out = (float*)d_out;

    cudaFuncSetAttribute(gemm_kernel<0>, cudaFuncAttributeMaxDynamicSharedMemorySize, SMEM_TOTAL);
    cudaFuncSetAttribute(gemm_kernel<1>, cudaFuncAttributeMaxDynamicSharedMemorySize, SMEM_TOTAL);
    cudaFuncSetAttribute(gemm_kernel<2>, cudaFuncAttributeMaxDynamicSharedMemorySize, SMEM_TOTAL);

    split_z_kernel<<<(M_ * TD / 4) / 256, 256>>>(zr, zi);
    build_w_kernel<<<(3 * TD * TD / 4) / 256, 256>>>(wqr, wqi, wkr, wki, wvr, wvi);
    gemm_kernel<0><<<dim3(3 * TD / BN, M_ / BM), 256, SMEM_TOTAL>>>(nullptr);
    gemm_kernel<1><<<dim3(136, 1, B_), 256, SMEM_TOTAL>>>(nullptr);   // lower-tri blocks
    softmax_split_kernel<<<B_ * S_, 256>>>();
    gemm_kernel<2><<<dim3(TD / BN, S_ / BM, B_), 256, SMEM_TOTAL>>>(out);
}